// round 14
// baseline (speedup 1.0000x reference)
#include <cuda_runtime.h>
#include <math.h>

// Fixed problem shapes
#define DIM     32
#define NN      32          // neighbors per entity
#define NRELS   64
#define RP      33          // padded pitch for rel table in smem
#define TPB     256         // 8 warps/block
#define NWARP   8
#define NDRUG   2000
#define MAXB    4096

__device__ int g_first[NDRUG];   // representative batch index per drug id

__device__ __forceinline__ float wmax(float v) {
#pragma unroll
    for (int o = 16; o; o >>= 1) v = fmaxf(v, __shfl_xor_sync(0xffffffffu, v, o));
    return v;
}
__device__ __forceinline__ float wsum(float v) {
#pragma unroll
    for (int o = 16; o; o >>= 1) v += __shfl_xor_sync(0xffffffffu, v, o);
    return v;
}

// ---- dedup helpers ----
__global__ void init_first_kernel() {
    const int i = blockIdx.x * blockDim.x + threadIdx.x;
    if (i < NDRUG) g_first[i] = 0x7fffffff;
}

__global__ void argmin_kernel(const int* __restrict__ drug, int B) {
    const int b = blockIdx.x * blockDim.x + threadIdx.x;
    if (b < B) atomicMin(&g_first[drug[b]], b);
}

__global__ void scatter_kernel(const int* __restrict__ drug,
                               float* __restrict__ out, int B) {
    const int i = blockIdx.x * blockDim.x + threadIdx.x;
    if (i >= B * DIM) return;
    const int b    = i / DIM;
    const int lane = i - b * DIM;
    const int rep  = g_first[drug[b]];
    if (rep != b) out[b * DIM + lane] = out[rep * DIM + lane];
}

// ---------------------------------------------------------------------------
// Fused KGCN (R13 proven body). One block (8 warps) per batch element;
// duplicate-drug blocks exit immediately, results scattered afterwards.
// ---------------------------------------------------------------------------
__global__ __launch_bounds__(TPB)
void kgcn_fused_kernel(const int* __restrict__ drug,
                       const int* __restrict__ adj_e,
                       const int* __restrict__ adj_r,
                       const float* __restrict__ ent,
                       const float* __restrict__ rel,
                       const float* __restrict__ W,
                       const float* __restrict__ bias,
                       float* __restrict__ out)
{
    const int b  = blockIdx.x;
    const int e0 = drug[b];
    if (g_first[e0] != b) return;            // duplicate drug: skip all work

    __shared__ float rel_s[NRELS * RP];      // 8448 B
    __shared__ float W_s[DIM * DIM];         // 4096 B  W_s[d][j]
    __shared__ float b_s[DIM];
    __shared__ float out1[NN * DIM];         // hop-1 results
    __shared__ float v0_s[DIM];
    __shared__ float sv_s[NWARP][32];
    __shared__ float sc_s[NWARP][32];
    __shared__ int   en_s[NWARP][32];

    const int tid  = threadIdx.x;
    const int lane = tid & 31;
    const int w    = tid >> 5;

    for (int i = tid; i < NRELS * DIM; i += TPB)
        rel_s[(i >> 5) * RP + (i & 31)] = rel[i];
    for (int i = tid; i < DIM * DIM; i += TPB) W_s[i] = W[i];
    if (tid < DIM) b_s[tid] = bias[tid];
    __syncthreads();

    float* svb = sv_s[w];
    float* scb = sc_s[w];
    int*   enb = en_s[w];

    // ---------------- Phase A: 4 hop-1 nodes per warp ----------------
#pragma unroll
    for (int k = 0; k < 4; k++) {
        const int m  = w + k * NWARP;
        const int e1 = adj_e[e0 * NN + m];

        const float sv = ent[e1 * DIM + lane];       // coalesced row
        const int   en = adj_e[e1 * NN + lane];      // lane = neighbor n
        const int   rr = adj_r[e1 * NN + lane];

        __syncwarp();
        svb[lane] = sv;
        enb[lane] = en;
        __syncwarp();

        float s = 0.f;
#pragma unroll
        for (int d = 0; d < DIM; d++) s += svb[d] * rel_s[rr * RP + d];

        const float mx = wmax(s);
        const float ex = __expf(s - mx);
        const float sm = wsum(ex);
        scb[lane] = ex / sm;
        __syncwarp();

        float a = 0.f;
#pragma unroll
        for (int n = 0; n < NN; n++)
            a += scb[n] * ent[enb[n] * DIM + lane];

        const float h = sv + a;
        __syncwarp();
        svb[lane] = h;
        __syncwarp();

        float o = b_s[lane];
#pragma unroll
        for (int d = 0; d < DIM; d++) o += svb[d] * W_s[d * DIM + lane];

        out1[m * DIM + lane] = 1.f / (1.f + __expf(-o));   // sigmoid
    }

    // ---- hop-0 on warp 7 ----
    if (w == NWARP - 1) {
        const float sv = ent[e0 * DIM + lane];
        const int   en = adj_e[e0 * NN + lane];
        const int   rr = adj_r[e0 * NN + lane];

        __syncwarp();
        svb[lane] = sv;
        enb[lane] = en;
        __syncwarp();

        float s = 0.f;
#pragma unroll
        for (int d = 0; d < DIM; d++) s += svb[d] * rel_s[rr * RP + d];

        const float mx = wmax(s);
        const float ex = __expf(s - mx);
        const float sm = wsum(ex);
        scb[lane] = ex / sm;
        __syncwarp();

        float a = 0.f;
#pragma unroll
        for (int n = 0; n < NN; n++)
            a += scb[n] * ent[enb[n] * DIM + lane];

        const float h = sv + a;
        __syncwarp();
        svb[lane] = h;
        __syncwarp();

        float o = b_s[lane];
#pragma unroll
        for (int d = 0; d < DIM; d++) o += svb[d] * W_s[d * DIM + lane];

        v0_s[lane] = 1.f / (1.f + __expf(-o));
    }

    __syncthreads();

    // ---------------- Phase B: iteration 1 (warp 0) ----------------
    if (w == 0) {
        const float v0 = v0_s[lane];
        const int   rr = adj_r[e0 * NN + lane];

        __syncwarp();
        svb[lane] = v0;
        __syncwarp();

        float s = 0.f;
#pragma unroll
        for (int d = 0; d < DIM; d++) s += svb[d] * rel_s[rr * RP + d];

        const float mx = wmax(s);
        const float ex = __expf(s - mx);
        const float sm = wsum(ex);
        scb[lane] = ex / sm;
        __syncwarp();

        float a = 0.f;
#pragma unroll
        for (int n = 0; n < NN; n++)
            a += scb[n] * out1[n * DIM + lane];

        const float h = v0 + a;
        __syncwarp();
        svb[lane] = h;
        __syncwarp();

        float o = b_s[lane];
#pragma unroll
        for (int d = 0; d < DIM; d++) o += svb[d] * W_s[d * DIM + lane];

        out[b * DIM + lane] = tanhf(o);
    }
}

extern "C" void kernel_launch(void* const* d_in, const int* in_sizes, int n_in,
                              void* d_out, int out_size)
{
    const int*   drug  = (const int*)  d_in[0];  // [B]
    const int*   adj_e = (const int*)  d_in[1];  // [NUM_ENT, 32]
    const int*   adj_r = (const int*)  d_in[2];  // [NUM_ENT, 32]
    const float* ent   = (const float*)d_in[3];  // [NUM_ENT, 32]
    const float* rel   = (const float*)d_in[4];  // [64, 32]
    const float* W     = (const float*)d_in[5];  // [32, 32]
    const float* bias  = (const float*)d_in[6];  // [32]
    float* out = (float*)d_out;

    const int B = in_sizes[0];

    init_first_kernel<<<(NDRUG + 255) / 256, 256>>>();
    argmin_kernel<<<(B + 255) / 256, 256>>>(drug, B);
    kgcn_fused_kernel<<<B, TPB>>>(drug, adj_e, adj_r, ent, rel, W, bias, out);
    scatter_kernel<<<(B * DIM + 255) / 256, 256>>>(drug, out, B);
}

// round 15
// speedup vs baseline: 1.0259x; 1.0259x over previous
#include <cuda_runtime.h>
#include <math.h>

// Fixed problem shapes
#define DIM     32
#define NN      32          // neighbors per entity
#define NRELS   64
#define RP      33          // padded pitch for rel table in smem
#define TPB     256         // 8 warps/block
#define NWARP   8
#define MAXB    4096

__device__ int g_rep[MAXB];   // representative batch index for each b

__device__ __forceinline__ float wmax(float v) {
#pragma unroll
    for (int o = 16; o; o >>= 1) v = fmaxf(v, __shfl_xor_sync(0xffffffffu, v, o));
    return v;
}
__device__ __forceinline__ float wsum(float v) {
#pragma unroll
    for (int o = 16; o; o >>= 1) v += __shfl_xor_sync(0xffffffffu, v, o);
    return v;
}
__device__ __forceinline__ int wmin_i(int v) {
#pragma unroll
    for (int o = 16; o; o >>= 1) v = min(v, __shfl_xor_sync(0xffffffffu, v, o));
    return v;
}

// Copy duplicate outputs from their representatives.
__global__ void scatter_kernel(float* __restrict__ out, int B) {
    const int i = blockIdx.x * blockDim.x + threadIdx.x;
    if (i >= B * DIM) return;
    const int b    = i >> 5;
    const int lane = i & 31;
    const int rep  = g_rep[b];
    if (rep != b) out[i] = out[rep * DIM + lane];
}

// ---------------------------------------------------------------------------
// Fused KGCN (R13 proven body) with inline dedup:
// each block scans drug[0..b-1]; if an earlier block has the same drug id it
// records the representative and exits before doing any work.
// ---------------------------------------------------------------------------
__global__ __launch_bounds__(TPB)
void kgcn_fused_kernel(const int* __restrict__ drug,
                       const int* __restrict__ adj_e,
                       const int* __restrict__ adj_r,
                       const float* __restrict__ ent,
                       const float* __restrict__ rel,
                       const float* __restrict__ W,
                       const float* __restrict__ bias,
                       float* __restrict__ out,
                       int B)
{
    __shared__ float rel_s[NRELS * RP];      // 8448 B
    __shared__ float W_s[DIM * DIM];         // 4096 B  W_s[d][j]
    __shared__ float b_s[DIM];
    __shared__ float out1[NN * DIM];         // hop-1 results
    __shared__ float v0_s[DIM];
    __shared__ float sv_s[NWARP][32];
    __shared__ float sc_s[NWARP][32];
    __shared__ int   en_s[NWARP][32];
    __shared__ int   rep_sh;

    const int tid  = threadIdx.x;
    const int lane = tid & 31;
    const int w    = tid >> 5;
    const int b    = blockIdx.x;
    const int e0   = drug[b];

    // ---- inline representative detection: min b' <= b with drug[b']==e0 ----
    if (tid == 0) rep_sh = b;
    __syncthreads();
    int myMin = b;
    for (int i = tid; i < b; i += TPB)
        if (drug[i] == e0) myMin = min(myMin, i);
    myMin = wmin_i(myMin);
    if (lane == 0 && myMin < b) atomicMin(&rep_sh, myMin);
    __syncthreads();
    const int rep = rep_sh;
    if (tid == 0) g_rep[b] = rep;
    if (rep != b) return;                    // duplicate: skip all work

    // ---- load tables into shared ----
    for (int i = tid; i < NRELS * DIM; i += TPB)
        rel_s[(i >> 5) * RP + (i & 31)] = rel[i];
    for (int i = tid; i < DIM * DIM; i += TPB) W_s[i] = W[i];
    if (tid < DIM) b_s[tid] = bias[tid];
    __syncthreads();

    float* svb = sv_s[w];
    float* scb = sc_s[w];
    int*   enb = en_s[w];

    // ---------------- Phase A: 4 hop-1 nodes per warp ----------------
#pragma unroll
    for (int k = 0; k < 4; k++) {
        const int m  = w + k * NWARP;
        const int e1 = adj_e[e0 * NN + m];

        const float sv = ent[e1 * DIM + lane];       // coalesced row
        const int   en = adj_e[e1 * NN + lane];      // lane = neighbor n
        const int   rr = adj_r[e1 * NN + lane];

        __syncwarp();
        svb[lane] = sv;
        enb[lane] = en;
        __syncwarp();

        float s = 0.f;
#pragma unroll
        for (int d = 0; d < DIM; d++) s += svb[d] * rel_s[rr * RP + d];

        const float mx = wmax(s);
        const float ex = __expf(s - mx);
        const float sm = wsum(ex);
        scb[lane] = ex / sm;
        __syncwarp();

        float a = 0.f;
#pragma unroll
        for (int n = 0; n < NN; n++)
            a += scb[n] * ent[enb[n] * DIM + lane];

        const float h = sv + a;
        __syncwarp();
        svb[lane] = h;
        __syncwarp();

        float o = b_s[lane];
#pragma unroll
        for (int d = 0; d < DIM; d++) o += svb[d] * W_s[d * DIM + lane];

        out1[m * DIM + lane] = 1.f / (1.f + __expf(-o));   // sigmoid
    }

    // ---- hop-0 on warp 7 ----
    if (w == NWARP - 1) {
        const float sv = ent[e0 * DIM + lane];
        const int   en = adj_e[e0 * NN + lane];
        const int   rr = adj_r[e0 * NN + lane];

        __syncwarp();
        svb[lane] = sv;
        enb[lane] = en;
        __syncwarp();

        float s = 0.f;
#pragma unroll
        for (int d = 0; d < DIM; d++) s += svb[d] * rel_s[rr * RP + d];

        const float mx = wmax(s);
        const float ex = __expf(s - mx);
        const float sm = wsum(ex);
        scb[lane] = ex / sm;
        __syncwarp();

        float a = 0.f;
#pragma unroll
        for (int n = 0; n < NN; n++)
            a += scb[n] * ent[enb[n] * DIM + lane];

        const float h = sv + a;
        __syncwarp();
        svb[lane] = h;
        __syncwarp();

        float o = b_s[lane];
#pragma unroll
        for (int d = 0; d < DIM; d++) o += svb[d] * W_s[d * DIM + lane];

        v0_s[lane] = 1.f / (1.f + __expf(-o));
    }

    __syncthreads();

    // ---------------- Phase B: iteration 1 (warp 0) ----------------
    if (w == 0) {
        const float v0 = v0_s[lane];
        const int   rr = adj_r[e0 * NN + lane];

        __syncwarp();
        svb[lane] = v0;
        __syncwarp();

        float s = 0.f;
#pragma unroll
        for (int d = 0; d < DIM; d++) s += svb[d] * rel_s[rr * RP + d];

        const float mx = wmax(s);
        const float ex = __expf(s - mx);
        const float sm = wsum(ex);
        scb[lane] = ex / sm;
        __syncwarp();

        float a = 0.f;
#pragma unroll
        for (int n = 0; n < NN; n++)
            a += scb[n] * out1[n * DIM + lane];

        const float h = v0 + a;
        __syncwarp();
        svb[lane] = h;
        __syncwarp();

        float o = b_s[lane];
#pragma unroll
        for (int d = 0; d < DIM; d++) o += svb[d] * W_s[d * DIM + lane];

        out[b * DIM + lane] = tanhf(o);
    }
}

extern "C" void kernel_launch(void* const* d_in, const int* in_sizes, int n_in,
                              void* d_out, int out_size)
{
    const int*   drug  = (const int*)  d_in[0];  // [B]
    const int*   adj_e = (const int*)  d_in[1];  // [NUM_ENT, 32]
    const int*   adj_r = (const int*)  d_in[2];  // [NUM_ENT, 32]
    const float* ent   = (const float*)d_in[3];  // [NUM_ENT, 32]
    const float* rel   = (const float*)d_in[4];  // [64, 32]
    const float* W     = (const float*)d_in[5];  // [32, 32]
    const float* bias  = (const float*)d_in[6];  // [32]
    float* out = (float*)d_out;

    const int B = in_sizes[0];

    kgcn_fused_kernel<<<B, TPB>>>(drug, adj_e, adj_r, ent, rel, W, bias, out, B);
    scatter_kernel<<<(B * DIM + 255) / 256, 256>>>(out, B);
}

// round 17
// speedup vs baseline: 1.0508x; 1.0242x over previous
#include <cuda_runtime.h>
#include <math.h>

// Fixed problem shapes
#define DIM     32
#define NN      32          // neighbors per entity
#define NRELS   64
#define RP      33          // padded pitch for rel table in smem
#define TPB     256         // 8 warps/block
#define NWARP   8
#define MAXDUP  256

__device__ __forceinline__ float wmax(float v) {
#pragma unroll
    for (int o = 16; o; o >>= 1) v = fmaxf(v, __shfl_xor_sync(0xffffffffu, v, o));
    return v;
}
__device__ __forceinline__ float wsum(float v) {
#pragma unroll
    for (int o = 16; o; o >>= 1) v += __shfl_xor_sync(0xffffffffu, v, o);
    return v;
}
__device__ __forceinline__ int wmin_i(int v) {
#pragma unroll
    for (int o = 16; o; o >>= 1) v = min(v, __shfl_xor_sync(0xffffffffu, v, o));
    return v;
}

// ---------------------------------------------------------------------------
// Fused KGCN with single-launch dedup:
// Each block scans drug[]. If an earlier block shares its drug id, exit.
// Otherwise (representative) it computes the tree once and, at the end,
// writes the final vector to EVERY batch row with this drug id.
// ---------------------------------------------------------------------------
__global__ __launch_bounds__(TPB)
void kgcn_fused_kernel(const int* __restrict__ drug,
                       const int* __restrict__ adj_e,
                       const int* __restrict__ adj_r,
                       const float* __restrict__ ent,
                       const float* __restrict__ rel,
                       const float* __restrict__ W,
                       const float* __restrict__ bias,
                       float* __restrict__ out,
                       int B)
{
    __shared__ float rel_s[NRELS * RP];      // 8448 B
    __shared__ float W_s[DIM * DIM];         // 4096 B  W_s[d][j]
    __shared__ float b_s[DIM];
    __shared__ float out1[NN * DIM];         // hop-1 results
    __shared__ float v0_s[DIM];
    __shared__ float sv_s[NWARP][32];
    __shared__ float sc_s[NWARP][32];
    __shared__ int   en_s[NWARP][32];
    __shared__ int   dup_list[MAXDUP];       // batch rows sharing this drug id
    __shared__ int   dup_cnt;
    __shared__ int   rep_sh;

    const int tid  = threadIdx.x;
    const int lane = tid & 31;
    const int w    = tid >> 5;
    const int b    = blockIdx.x;
    const int e0   = drug[b];

    // ---- dedup scan over the whole batch (drug[] is 4KB, L1/L2 resident) ----
    if (tid == 0) { dup_cnt = 0; rep_sh = b; }
    __syncthreads();
    int myMin = b;
    for (int i = tid; i < B; i += TPB) {
        if (drug[i] == e0) {
            myMin = min(myMin, i);
            const int slot = atomicAdd(&dup_cnt, 1);
            if (slot < MAXDUP) dup_list[slot] = i;
        }
    }
    myMin = wmin_i(myMin);
    if (lane == 0) atomicMin(&rep_sh, myMin);
    __syncthreads();
    if (rep_sh != b) return;                 // duplicate: rep block handles us

    // ---- load tables into shared ----
    for (int i = tid; i < NRELS * DIM; i += TPB)
        rel_s[(i >> 5) * RP + (i & 31)] = rel[i];
    for (int i = tid; i < DIM * DIM; i += TPB) W_s[i] = W[i];
    if (tid < DIM) b_s[tid] = bias[tid];
    __syncthreads();

    float* svb = sv_s[w];
    float* scb = sc_s[w];
    int*   enb = en_s[w];

    // ---------------- Phase A: 4 hop-1 nodes per warp ----------------
#pragma unroll
    for (int k = 0; k < 4; k++) {
        const int m  = w + k * NWARP;
        const int e1 = adj_e[e0 * NN + m];

        const float sv = ent[e1 * DIM + lane];       // coalesced row
        const int   en = adj_e[e1 * NN + lane];      // lane = neighbor n
        const int   rr = adj_r[e1 * NN + lane];

        __syncwarp();
        svb[lane] = sv;
        enb[lane] = en;
        __syncwarp();

        float s = 0.f;
#pragma unroll
        for (int d = 0; d < DIM; d++) s += svb[d] * rel_s[rr * RP + d];

        const float mx = wmax(s);
        const float ex = __expf(s - mx);
        const float sm = wsum(ex);
        scb[lane] = ex / sm;
        __syncwarp();

        float a = 0.f;
#pragma unroll
        for (int n = 0; n < NN; n++)
            a += scb[n] * ent[enb[n] * DIM + lane];

        const float h = sv + a;
        __syncwarp();
        svb[lane] = h;
        __syncwarp();

        float o = b_s[lane];
#pragma unroll
        for (int d = 0; d < DIM; d++) o += svb[d] * W_s[d * DIM + lane];

        out1[m * DIM + lane] = 1.f / (1.f + __expf(-o));   // sigmoid
    }

    // ---- hop-0 on warp 7 ----
    if (w == NWARP - 1) {
        const float sv = ent[e0 * DIM + lane];
        const int   en = adj_e[e0 * NN + lane];
        const int   rr = adj_r[e0 * NN + lane];

        __syncwarp();
        svb[lane] = sv;
        enb[lane] = en;
        __syncwarp();

        float s = 0.f;
#pragma unroll
        for (int d = 0; d < DIM; d++) s += svb[d] * rel_s[rr * RP + d];

        const float mx = wmax(s);
        const float ex = __expf(s - mx);
        const float sm = wsum(ex);
        scb[lane] = ex / sm;
        __syncwarp();

        float a = 0.f;
#pragma unroll
        for (int n = 0; n < NN; n++)
            a += scb[n] * ent[enb[n] * DIM + lane];

        const float h = sv + a;
        __syncwarp();
        svb[lane] = h;
        __syncwarp();

        float o = b_s[lane];
#pragma unroll
        for (int d = 0; d < DIM; d++) o += svb[d] * W_s[d * DIM + lane];

        v0_s[lane] = 1.f / (1.f + __expf(-o));
    }

    __syncthreads();

    // ---------------- Phase B: iteration 1 (warp 0) ----------------
    if (w == 0) {
        const float v0 = v0_s[lane];
        const int   rr = adj_r[e0 * NN + lane];

        __syncwarp();
        svb[lane] = v0;
        __syncwarp();

        float s = 0.f;
#pragma unroll
        for (int d = 0; d < DIM; d++) s += svb[d] * rel_s[rr * RP + d];

        const float mx = wmax(s);
        const float ex = __expf(s - mx);
        const float sm = wsum(ex);
        scb[lane] = ex / sm;
        __syncwarp();

        float a = 0.f;
#pragma unroll
        for (int n = 0; n < NN; n++)
            a += scb[n] * out1[n * DIM + lane];

        const float h = v0 + a;
        __syncwarp();
        svb[lane] = h;
        __syncwarp();

        float o = b_s[lane];
#pragma unroll
        for (int d = 0; d < DIM; d++) o += svb[d] * W_s[d * DIM + lane];

        const float val = tanhf(o);

        // write result to every batch row that shares this drug id
        const int cnt = dup_cnt;
        if (cnt <= MAXDUP) {
            for (int j = 0; j < cnt; j++)
                out[dup_list[j] * DIM + lane] = val;
        } else {
            for (int i = 0; i < B; i++)
                if (drug[i] == e0) out[i * DIM + lane] = val;
        }
    }
}

extern "C" void kernel_launch(void* const* d_in, const int* in_sizes, int n_in,
                              void* d_out, int out_size)
{
    const int*   drug  = (const int*)  d_in[0];  // [B]
    const int*   adj_e = (const int*)  d_in[1];  // [NUM_ENT, 32]
    const int*   adj_r = (const int*)  d_in[2];  // [NUM_ENT, 32]
    const float* ent   = (const float*)d_in[3];  // [NUM_ENT, 32]
    const float* rel   = (const float*)d_in[4];  // [64, 32]
    const float* W     = (const float*)d_in[5];  // [32, 32]
    const float* bias  = (const float*)d_in[6];  // [32]
    float* out = (float*)d_out;

    const int B = in_sizes[0];
    kgcn_fused_kernel<<<B, TPB>>>(drug, adj_e, adj_r, ent, rel, W, bias, out, B);
}